// round 2
// baseline (speedup 1.0000x reference)
#include <cuda_runtime.h>
#include <cstdint>

#define H        128
#define NE       500000
#define NNODES   50000
#define WARPS    8
#define ET       8                 // edges per warp per tile
#define TILE_E   (WARPS * ET)      // 64 edges per block-tile
#define NTHREADS 256

// ---------------- packed f32x2 helpers (Blackwell) ----------------
__device__ __forceinline__ unsigned long long pk2(float lo, float hi) {
    unsigned long long r;
    asm("mov.b64 %0, {%1, %2};" : "=l"(r) : "f"(lo), "f"(hi));
    return r;
}
__device__ __forceinline__ float2 upk2(unsigned long long v) {
    float2 f;
    asm("mov.b64 {%0, %1}, %2;" : "=f"(f.x), "=f"(f.y) : "l"(v));
    return f;
}
__device__ __forceinline__ unsigned long long ffma2(unsigned long long a,
                                                    unsigned long long b,
                                                    unsigned long long c) {
    unsigned long long d;
    asm("fma.rn.f32x2 %0, %1, %2, %3;" : "=l"(d) : "l"(a), "l"(b), "l"(c));
    return d;
}

// ---------------- out = x (init before scatter-add) ----------------
__global__ void copy_x_kernel(const float4* __restrict__ x,
                              float4* __restrict__ out, int n) {
    int i = blockIdx.x * blockDim.x + threadIdx.x;
    if (i < n) out[i] = x[i];
}

// ---------------- main fused edge-MLP + scatter kernel ----------------
__global__ __launch_bounds__(NTHREADS, 1)
void edge_mlp_kernel(const float* __restrict__ x,
                     const int* __restrict__ ei,         // [2, NE] int32
                     const float* __restrict__ ea,       // [NE]
                     const float* __restrict__ W1,       // [256, 128]
                     const float* __restrict__ b1,       // [128]
                     const float* __restrict__ W2,       // [128, 128]
                     const float* __restrict__ b2,       // [128]
                     float* __restrict__ out)            // [NNODES, 128]
{
    extern __shared__ float smem[];
    float* sW1 = smem;                  // 256*128 = 128 KB
    float* sW2 = sW1 + 256 * H;         // 128*128 =  64 KB
    float* sX  = sW2 + H * H;           // WARPS*ET*128 = 32 KB

    // Cooperative load of both weight matrices into SMEM (float4).
    {
        const float4* g1 = (const float4*)W1;
        float4* s1 = (float4*)sW1;
        for (int i = threadIdx.x; i < 256 * H / 4; i += blockDim.x) s1[i] = g1[i];
        const float4* g2 = (const float4*)W2;
        float4* s2 = (float4*)sW2;
        for (int i = threadIdx.x; i < H * H / 4; i += blockDim.x) s2[i] = g2[i];
    }
    __syncthreads();

    const int warp = threadIdx.x >> 5;
    const int lane = threadIdx.x & 31;
    float* myX = sX + warp * (ET * H);

    const float4 b1v = ((const float4*)b1)[lane];
    const float4 b2v = ((const float4*)b2)[lane];
    const unsigned long long b1p0 = pk2(b1v.x, b1v.y), b1p1 = pk2(b1v.z, b1v.w);
    const unsigned long long b2p0 = pk2(b2v.x, b2v.y), b2p1 = pk2(b2v.z, b2v.w);

    const int ntiles = (NE + TILE_E - 1) / TILE_E;
    for (int tile = blockIdx.x; tile < ntiles; tile += gridDim.x) {
        const int ebase = tile * TILE_E + warp * ET;

        unsigned long long acc[ET][2];
        #pragma unroll
        for (int e = 0; e < ET; e++) { acc[e][0] = b1p0; acc[e][1] = b1p1; }

        // GEMM1 in two phases: ph=0 uses x[src] vs W1 rows [0,128),
        //                      ph=1 uses x[dst] vs W1 rows [128,256).
        #pragma unroll
        for (int ph = 0; ph < 2; ph++) {
            // Gather this warp's 8 node rows (coalesced 512 B rows).
            #pragma unroll
            for (int e = 0; e < ET; e++) {
                int edge = ebase + e;
                if (edge < NE) {
                    int node = ei[ph * NE + edge];
                    float4 v = ((const float4*)(x + (size_t)node * H))[lane];
                    ((float4*)(myX + e * H))[lane] = v;
                }
            }
            __syncwarp();

            const float* sW = sW1 + ph * 128 * H;
            for (int k = 0; k < H; k += 2) {
                float4 wA = *(const float4*)(sW + k * H + 4 * lane);
                float4 wB = *(const float4*)(sW + (k + 1) * H + 4 * lane);
                unsigned long long wA01 = pk2(wA.x, wA.y), wA23 = pk2(wA.z, wA.w);
                unsigned long long wB01 = pk2(wB.x, wB.y), wB23 = pk2(wB.z, wB.w);
                #pragma unroll
                for (int e = 0; e < ET; e++) {
                    float2 h2 = *(const float2*)(myX + e * H + k);  // broadcast
                    unsigned long long h0 = pk2(h2.x, h2.x);
                    unsigned long long h1 = pk2(h2.y, h2.y);
                    acc[e][0] = ffma2(h0, wA01, acc[e][0]);
                    acc[e][1] = ffma2(h0, wA23, acc[e][1]);
                    acc[e][0] = ffma2(h1, wB01, acc[e][0]);
                    acc[e][1] = ffma2(h1, wB23, acc[e][1]);
                }
            }
            __syncwarp();
        }

        // relu, stash m1 into the (now free) x-tile, re-init acc with b2
        #pragma unroll
        for (int e = 0; e < ET; e++) {
            float2 a = upk2(acc[e][0]);
            float2 b = upk2(acc[e][1]);
            float4 m = make_float4(fmaxf(a.x, 0.f), fmaxf(a.y, 0.f),
                                   fmaxf(b.x, 0.f), fmaxf(b.y, 0.f));
            ((float4*)(myX + e * H))[lane] = m;
            acc[e][0] = b2p0; acc[e][1] = b2p1;
        }
        __syncwarp();

        // GEMM2: m2 = relu(m1) @ W2 + b2
        for (int k = 0; k < H; k += 2) {
            float4 wA = *(const float4*)(sW2 + k * H + 4 * lane);
            float4 wB = *(const float4*)(sW2 + (k + 1) * H + 4 * lane);
            unsigned long long wA01 = pk2(wA.x, wA.y), wA23 = pk2(wA.z, wA.w);
            unsigned long long wB01 = pk2(wB.x, wB.y), wB23 = pk2(wB.z, wB.w);
            #pragma unroll
            for (int e = 0; e < ET; e++) {
                float2 h2 = *(const float2*)(myX + e * H + k);
                unsigned long long h0 = pk2(h2.x, h2.x);
                unsigned long long h1 = pk2(h2.y, h2.y);
                acc[e][0] = ffma2(h0, wA01, acc[e][0]);
                acc[e][1] = ffma2(h0, wA23, acc[e][1]);
                acc[e][0] = ffma2(h1, wB01, acc[e][0]);
                acc[e][1] = ffma2(h1, wB23, acc[e][1]);
            }
        }

        // scale by edge_attr and scatter-add (vectorized red.global)
        #pragma unroll
        for (int e = 0; e < ET; e++) {
            int edge = ebase + e;
            if (edge < NE) {
                float w = ea[edge];
                int dst = ei[NE + edge];
                float2 a = upk2(acc[e][0]);
                float2 b = upk2(acc[e][1]);
                float* p = out + (size_t)dst * H + 4 * lane;
                asm volatile("red.global.add.v4.f32 [%0], {%1, %2, %3, %4};"
                             :: "l"(p), "f"(a.x * w), "f"(a.y * w),
                                "f"(b.x * w), "f"(b.y * w)
                             : "memory");
            }
        }
        __syncwarp();   // protect myX before next tile's gather
    }
}

// ---------------- launch ----------------
extern "C" void kernel_launch(void* const* d_in, const int* in_sizes, int n_in,
                              void* d_out, int out_size) {
    (void)in_sizes; (void)n_in; (void)out_size;
    const float* x  = (const float*)d_in[0];
    const int*   ei = (const int*)d_in[1];
    const float* ea = (const float*)d_in[2];
    const float* W1 = (const float*)d_in[3];
    const float* b1 = (const float*)d_in[4];
    const float* W2 = (const float*)d_in[5];
    const float* b2 = (const float*)d_in[6];
    float* out = (float*)d_out;

    const int ncopy = NNODES * H / 4;
    copy_x_kernel<<<(ncopy + 255) / 256, 256>>>((const float4*)x, (float4*)out, ncopy);

    const size_t smem_bytes = (size_t)(256 * H + H * H + WARPS * ET * H) * sizeof(float);
    cudaFuncSetAttribute(edge_mlp_kernel,
                         cudaFuncAttributeMaxDynamicSharedMemorySize,
                         (int)smem_bytes);
    edge_mlp_kernel<<<148, NTHREADS, smem_bytes>>>(x, ei, ea, W1, b1, W2, b2, out);
}

// round 4
// speedup vs baseline: 4.5034x; 4.5034x over previous
#include <cuda_runtime.h>
#include <cstdint>

#define H        128
#define NE       500000
#define NN       50000
#define TILE_R   64                 // node rows per block tile (8 warps x 8)
#define NTILES_N ((NN + TILE_R - 1) / TILE_R)
#define GRID_G   148

// ---------------- scratch (__device__ globals: allowed) ----------------
__device__ __align__(16) float g_U[NN * H];     // x@W1a + b1
__device__ __align__(16) float g_V[NN * H];     // x@W1b
__device__ __align__(16) float g_S[NN * H];     // sum_e ea*relu(u+v) per dst
__device__ __align__(16) float g_sumw[NN];      // sum_e ea per dst

// ---------------- packed f32x2 helpers ----------------
__device__ __forceinline__ unsigned long long pk2(float lo, float hi) {
    unsigned long long r;
    asm("mov.b64 %0, {%1, %2};" : "=l"(r) : "f"(lo), "f"(hi));
    return r;
}
__device__ __forceinline__ float2 upk2(unsigned long long v) {
    float2 f;
    asm("mov.b64 {%0, %1}, %2;" : "=f"(f.x), "=f"(f.y) : "l"(v));
    return f;
}
__device__ __forceinline__ unsigned long long ffma2(unsigned long long a,
                                                    unsigned long long b,
                                                    unsigned long long c) {
    unsigned long long d;
    asm("fma.rn.f32x2 %0, %1, %2, %3;" : "=l"(d) : "l"(a), "l"(b), "l"(c));
    return d;
}

// ---------------- zero S and sumw ----------------
__global__ void zero_kernel() {
    int i = blockIdx.x * blockDim.x + threadIdx.x;
    if (i < NN * H / 4) ((float4*)g_S)[i] = make_float4(0.f, 0.f, 0.f, 0.f);
    else if (i < NN * H / 4 + NN / 4)
        ((float4*)g_sumw)[i - NN * H / 4] = make_float4(0.f, 0.f, 0.f, 0.f);
}

// ---------------- GEMM1: U = x@W1[0:128] + b1 ; V = x@W1[128:256] ----------------
__global__ __launch_bounds__(256, 1)
void gemm1_kernel(const float* __restrict__ x,
                  const float* __restrict__ W1,   // [256,128]
                  const float* __restrict__ b1)
{
    extern __shared__ float smem[];
    float* sW = smem;                 // 256*128 = 128 KB
    float* sX = sW + 256 * H;         // 8 warps * 8 rows * 128 = 16 KB

    {
        const float4* g = (const float4*)W1;
        float4* s = (float4*)sW;
        for (int i = threadIdx.x; i < 256 * H / 4; i += blockDim.x) s[i] = g[i];
    }
    __syncthreads();

    const int warp = threadIdx.x >> 5, lane = threadIdx.x & 31;
    float* myX = sX + warp * (8 * H);

    const float4 b1v = ((const float4*)b1)[lane];
    const unsigned long long b1p0 = pk2(b1v.x, b1v.y), b1p1 = pk2(b1v.z, b1v.w);

    for (int tile = blockIdx.x; tile < NTILES_N; tile += GRID_G) {
        const int rbase = tile * TILE_R + warp * 8;

        #pragma unroll
        for (int e = 0; e < 8; e++) {
            int r = rbase + e;
            if (r < NN)
                ((float4*)(myX + e * H))[lane] = ((const float4*)(x + (size_t)r * H))[lane];
        }
        __syncwarp();

        unsigned long long aU[8][2], aV[8][2];
        #pragma unroll
        for (int e = 0; e < 8; e++) {
            aU[e][0] = b1p0; aU[e][1] = b1p1;
            aV[e][0] = 0ull; aV[e][1] = 0ull;
        }

        for (int k = 0; k < H; k += 2) {
            float4 u0 = *(const float4*)(sW + k * H + 4 * lane);
            float4 u1 = *(const float4*)(sW + (k + 1) * H + 4 * lane);
            float4 v0 = *(const float4*)(sW + (128 + k) * H + 4 * lane);
            float4 v1 = *(const float4*)(sW + (129 + k) * H + 4 * lane);
            unsigned long long u0a = pk2(u0.x, u0.y), u0b = pk2(u0.z, u0.w);
            unsigned long long u1a = pk2(u1.x, u1.y), u1b = pk2(u1.z, u1.w);
            unsigned long long v0a = pk2(v0.x, v0.y), v0b = pk2(v0.z, v0.w);
            unsigned long long v1a = pk2(v1.x, v1.y), v1b = pk2(v1.z, v1.w);
            #pragma unroll
            for (int e = 0; e < 8; e++) {
                float2 h2 = *(const float2*)(myX + e * H + k);   // broadcast
                unsigned long long h0 = pk2(h2.x, h2.x);
                unsigned long long h1 = pk2(h2.y, h2.y);
                aU[e][0] = ffma2(h0, u0a, aU[e][0]);
                aU[e][1] = ffma2(h0, u0b, aU[e][1]);
                aU[e][0] = ffma2(h1, u1a, aU[e][0]);
                aU[e][1] = ffma2(h1, u1b, aU[e][1]);
                aV[e][0] = ffma2(h0, v0a, aV[e][0]);
                aV[e][1] = ffma2(h0, v0b, aV[e][1]);
                aV[e][0] = ffma2(h1, v1a, aV[e][0]);
                aV[e][1] = ffma2(h1, v1b, aV[e][1]);
            }
        }

        #pragma unroll
        for (int e = 0; e < 8; e++) {
            int r = rbase + e;
            if (r < NN) {
                float2 a = upk2(aU[e][0]), b = upk2(aU[e][1]);
                ((float4*)(g_U + (size_t)r * H))[lane] = make_float4(a.x, a.y, b.x, b.y);
                float2 c = upk2(aV[e][0]), d = upk2(aV[e][1]);
                ((float4*)(g_V + (size_t)r * H))[lane] = make_float4(c.x, c.y, d.x, d.y);
            }
        }
        __syncwarp();
    }
}

// ---------------- edge kernel: S[dst] += ea*relu(U[src]+V[dst]); sumw[dst] += ea ----------------
__global__ __launch_bounds__(256)
void edge_kernel(const int* __restrict__ ei, const float* __restrict__ ea)
{
    const int lane = threadIdx.x & 31;
    const int gwarp = (blockIdx.x * blockDim.x + threadIdx.x) >> 5;
    const int nwarps = (gridDim.x * blockDim.x) >> 5;

    for (int e0 = gwarp * 2; e0 < NE; e0 += nwarps * 2) {
        int   s0 = ei[e0],      d0 = ei[NE + e0];
        float w0 = ea[e0];
        float4 u0 = ((const float4*)(g_U + (size_t)s0 * H))[lane];
        float4 v0 = ((const float4*)(g_V + (size_t)d0 * H))[lane];

        int e1 = e0 + 1;
        bool has1 = e1 < NE;
        int s1 = 0, d1 = 0; float w1 = 0.f;
        float4 u1 = make_float4(0, 0, 0, 0), v1 = u1;
        if (has1) {
            s1 = ei[e1]; d1 = ei[NE + e1]; w1 = ea[e1];
            u1 = ((const float4*)(g_U + (size_t)s1 * H))[lane];
            v1 = ((const float4*)(g_V + (size_t)d1 * H))[lane];
        }

        {
            float a0 = fmaxf(u0.x + v0.x, 0.f) * w0;
            float a1 = fmaxf(u0.y + v0.y, 0.f) * w0;
            float a2 = fmaxf(u0.z + v0.z, 0.f) * w0;
            float a3 = fmaxf(u0.w + v0.w, 0.f) * w0;
            float* p = g_S + (size_t)d0 * H + 4 * lane;
            asm volatile("red.global.add.v4.f32 [%0], {%1,%2,%3,%4};"
                         :: "l"(p), "f"(a0), "f"(a1), "f"(a2), "f"(a3) : "memory");
            if (lane == 0)
                asm volatile("red.global.add.f32 [%0], %1;"
                             :: "l"(g_sumw + d0), "f"(w0) : "memory");
        }
        if (has1) {
            float a0 = fmaxf(u1.x + v1.x, 0.f) * w1;
            float a1 = fmaxf(u1.y + v1.y, 0.f) * w1;
            float a2 = fmaxf(u1.z + v1.z, 0.f) * w1;
            float a3 = fmaxf(u1.w + v1.w, 0.f) * w1;
            float* p = g_S + (size_t)d1 * H + 4 * lane;
            asm volatile("red.global.add.v4.f32 [%0], {%1,%2,%3,%4};"
                         :: "l"(p), "f"(a0), "f"(a1), "f"(a2), "f"(a3) : "memory");
            if (lane == 0)
                asm volatile("red.global.add.f32 [%0], %1;"
                             :: "l"(g_sumw + d1), "f"(w1) : "memory");
        }
    }
}

// ---------------- GEMM2: out = x + S@W2 + b2*sumw ----------------
__global__ __launch_bounds__(256, 1)
void gemm2_kernel(const float* __restrict__ x,
                  const float* __restrict__ W2,   // [128,128]
                  const float* __restrict__ b2,
                  float* __restrict__ out)
{
    extern __shared__ float smem[];
    float* sW = smem;                 // 128*128 = 64 KB
    float* sS = sW + H * H;           // 16 KB

    {
        const float4* g = (const float4*)W2;
        float4* s = (float4*)sW;
        for (int i = threadIdx.x; i < H * H / 4; i += blockDim.x) s[i] = g[i];
    }
    __syncthreads();

    const int warp = threadIdx.x >> 5, lane = threadIdx.x & 31;
    float* myS = sS + warp * (8 * H);

    const float4 b2v = ((const float4*)b2)[lane];

    for (int tile = blockIdx.x; tile < NTILES_N; tile += GRID_G) {
        const int rbase = tile * TILE_R + warp * 8;

        #pragma unroll
        for (int e = 0; e < 8; e++) {
            int r = rbase + e;
            if (r < NN)
                ((float4*)(myS + e * H))[lane] = ((const float4*)(g_S + (size_t)r * H))[lane];
        }
        __syncwarp();

        unsigned long long acc[8][2];
        #pragma unroll
        for (int e = 0; e < 8; e++) { acc[e][0] = 0ull; acc[e][1] = 0ull; }

        for (int k = 0; k < H; k += 2) {
            float4 wA = *(const float4*)(sW + k * H + 4 * lane);
            float4 wB = *(const float4*)(sW + (k + 1) * H + 4 * lane);
            unsigned long long wA01 = pk2(wA.x, wA.y), wA23 = pk2(wA.z, wA.w);
            unsigned long long wB01 = pk2(wB.x, wB.y), wB23 = pk2(wB.z, wB.w);
            #pragma unroll
            for (int e = 0; e < 8; e++) {
                float2 h2 = *(const float2*)(myS + e * H + k);
                unsigned long long h0 = pk2(h2.x, h2.x);
                unsigned long long h1 = pk2(h2.y, h2.y);
                acc[e][0] = ffma2(h0, wA01, acc[e][0]);
                acc[e][1] = ffma2(h0, wA23, acc[e][1]);
                acc[e][0] = ffma2(h1, wB01, acc[e][0]);
                acc[e][1] = ffma2(h1, wB23, acc[e][1]);
            }
        }

        #pragma unroll
        for (int e = 0; e < 8; e++) {
            int r = rbase + e;
            if (r < NN) {
                float  sw = g_sumw[r];
                float4 xr = ((const float4*)(x + (size_t)r * H))[lane];
                float2 a = upk2(acc[e][0]), b = upk2(acc[e][1]);
                float4 o = make_float4(xr.x + a.x + b2v.x * sw,
                                       xr.y + a.y + b2v.y * sw,
                                       xr.z + b.x + b2v.z * sw,
                                       xr.w + b.y + b2v.w * sw);
                ((float4*)(out + (size_t)r * H))[lane] = o;
            }
        }
        __syncwarp();
    }
}

// ---------------- launch ----------------
extern "C" void kernel_launch(void* const* d_in, const int* in_sizes, int n_in,
                              void* d_out, int out_size) {
    (void)in_sizes; (void)n_in; (void)out_size;
    const float* x  = (const float*)d_in[0];
    const int*   ei = (const int*)d_in[1];
    const float* ea = (const float*)d_in[2];
    const float* W1 = (const float*)d_in[3];
    const float* b1 = (const float*)d_in[4];
    const float* W2 = (const float*)d_in[5];
    const float* b2 = (const float*)d_in[6];
    float* out = (float*)d_out;

    const int nz = NN * H / 4 + NN / 4;
    zero_kernel<<<(nz + 255) / 256, 256>>>();

    const size_t smem1 = (size_t)(256 * H + 8 * 8 * H) * sizeof(float);   // 144 KB
    cudaFuncSetAttribute(gemm1_kernel, cudaFuncAttributeMaxDynamicSharedMemorySize, (int)smem1);
    gemm1_kernel<<<GRID_G, 256, smem1>>>(x, W1, b1);

    edge_kernel<<<2048, 256>>>(ei, ea);

    const size_t smem2 = (size_t)(H * H + 8 * 8 * H) * sizeof(float);     // 80 KB
    cudaFuncSetAttribute(gemm2_kernel, cudaFuncAttributeMaxDynamicSharedMemorySize, (int)smem2);
    gemm2_kernel<<<GRID_G, 256, smem2>>>(x, W2, b2, out);
}

// round 5
// speedup vs baseline: 4.7622x; 1.0575x over previous
#include <cuda_runtime.h>
#include <cstdint>

#define H        128
#define NE       500000
#define NN       50000
#define GW       16                 // warps per GEMM block
#define TILE_R   (GW * 8)           // 128 node rows per block tile
#define NTILES_N ((NN + TILE_R - 1) / TILE_R)
#define GRID_G   148

// ---------------- scratch (__device__ globals: allowed) ----------------
__device__ __align__(16) float g_U[NN * H];     // x@W1a + b1
__device__ __align__(16) float g_V[NN * H];     // x@W1b
__device__ __align__(16) float g_S[NN * H];     // sum_e ea*relu(u+v) per dst
__device__ __align__(16) float g_sumw[NN];      // sum_e ea per dst

// ---------------- packed f32x2 helpers ----------------
__device__ __forceinline__ unsigned long long pk2(float lo, float hi) {
    unsigned long long r;
    asm("mov.b64 %0, {%1, %2};" : "=l"(r) : "f"(lo), "f"(hi));
    return r;
}
__device__ __forceinline__ float2 upk2(unsigned long long v) {
    float2 f;
    asm("mov.b64 {%0, %1}, %2;" : "=f"(f.x), "=f"(f.y) : "l"(v));
    return f;
}
__device__ __forceinline__ unsigned long long ffma2(unsigned long long a,
                                                    unsigned long long b,
                                                    unsigned long long c) {
    unsigned long long d;
    asm("fma.rn.f32x2 %0, %1, %2, %3;" : "=l"(d) : "l"(a), "l"(b), "l"(c));
    return d;
}

// ---------------- zero S and sumw ----------------
__global__ void zero_kernel() {
    int i = blockIdx.x * blockDim.x + threadIdx.x;
    if (i < NN * H / 4) ((float4*)g_S)[i] = make_float4(0.f, 0.f, 0.f, 0.f);
    else if (i < NN * H / 4 + NN / 4)
        ((float4*)g_sumw)[i - NN * H / 4] = make_float4(0.f, 0.f, 0.f, 0.f);
}

// ---------------- GEMM1: U = x@W1[0:128] + b1 ; V = x@W1[128:256] ----------------
__global__ __launch_bounds__(32 * GW, 1)
void gemm1_kernel(const float* __restrict__ x,
                  const float* __restrict__ W1,   // [256,128]
                  const float* __restrict__ b1)
{
    extern __shared__ float smem[];
    float* sW = smem;                 // 256*128 = 128 KB
    float* sX = sW + 256 * H;         // GW*8*128 = 64 KB

    {
        const float4* g = (const float4*)W1;
        float4* s = (float4*)sW;
        for (int i = threadIdx.x; i < 256 * H / 4; i += blockDim.x) s[i] = g[i];
    }
    __syncthreads();

    const int warp = threadIdx.x >> 5, lane = threadIdx.x & 31;
    float* myX = sX + warp * (8 * H);

    const float4 b1v = ((const float4*)b1)[lane];
    const unsigned long long b1p0 = pk2(b1v.x, b1v.y), b1p1 = pk2(b1v.z, b1v.w);

    for (int tile = blockIdx.x; tile < NTILES_N; tile += GRID_G) {
        const int rbase = tile * TILE_R + warp * 8;

        #pragma unroll
        for (int e = 0; e < 8; e++) {
            int r = rbase + e;
            if (r < NN)
                ((float4*)(myX + e * H))[lane] = ((const float4*)(x + (size_t)r * H))[lane];
        }
        __syncwarp();

        unsigned long long aU[8][2], aV[8][2];
        #pragma unroll
        for (int e = 0; e < 8; e++) {
            aU[e][0] = b1p0; aU[e][1] = b1p1;
            aV[e][0] = 0ull; aV[e][1] = 0ull;
        }

        for (int k = 0; k < H; k += 4) {
            unsigned long long uP[4][2], vP[4][2];
            #pragma unroll
            for (int j = 0; j < 4; j++) {
                float4 wu = *(const float4*)(sW + (k + j) * H + 4 * lane);
                uP[j][0] = pk2(wu.x, wu.y); uP[j][1] = pk2(wu.z, wu.w);
                float4 wv = *(const float4*)(sW + (128 + k + j) * H + 4 * lane);
                vP[j][0] = pk2(wv.x, wv.y); vP[j][1] = pk2(wv.z, wv.w);
            }
            #pragma unroll
            for (int e = 0; e < 8; e++) {
                float4 h = *(const float4*)(myX + e * H + k);   // broadcast LDS.128
                unsigned long long h0 = pk2(h.x, h.x), h1 = pk2(h.y, h.y);
                unsigned long long h2 = pk2(h.z, h.z), h3 = pk2(h.w, h.w);
                aU[e][0] = ffma2(h0, uP[0][0], aU[e][0]);
                aU[e][1] = ffma2(h0, uP[0][1], aU[e][1]);
                aU[e][0] = ffma2(h1, uP[1][0], aU[e][0]);
                aU[e][1] = ffma2(h1, uP[1][1], aU[e][1]);
                aU[e][0] = ffma2(h2, uP[2][0], aU[e][0]);
                aU[e][1] = ffma2(h2, uP[2][1], aU[e][1]);
                aU[e][0] = ffma2(h3, uP[3][0], aU[e][0]);
                aU[e][1] = ffma2(h3, uP[3][1], aU[e][1]);
                aV[e][0] = ffma2(h0, vP[0][0], aV[e][0]);
                aV[e][1] = ffma2(h0, vP[0][1], aV[e][1]);
                aV[e][0] = ffma2(h1, vP[1][0], aV[e][0]);
                aV[e][1] = ffma2(h1, vP[1][1], aV[e][1]);
                aV[e][0] = ffma2(h2, vP[2][0], aV[e][0]);
                aV[e][1] = ffma2(h2, vP[2][1], aV[e][1]);
                aV[e][0] = ffma2(h3, vP[3][0], aV[e][0]);
                aV[e][1] = ffma2(h3, vP[3][1], aV[e][1]);
            }
        }

        #pragma unroll
        for (int e = 0; e < 8; e++) {
            int r = rbase + e;
            if (r < NN) {
                float2 a = upk2(aU[e][0]), b = upk2(aU[e][1]);
                ((float4*)(g_U + (size_t)r * H))[lane] = make_float4(a.x, a.y, b.x, b.y);
                float2 c = upk2(aV[e][0]), d = upk2(aV[e][1]);
                ((float4*)(g_V + (size_t)r * H))[lane] = make_float4(c.x, c.y, d.x, d.y);
            }
        }
        __syncwarp();
    }
}

// ---------------- edge kernel: S[dst] += ea*relu(U[src]+V[dst]); sumw[dst] += ea ----------------
__global__ __launch_bounds__(256)
void edge_kernel(const int* __restrict__ ei, const float* __restrict__ ea)
{
    const int lane = threadIdx.x & 31;
    const int gwarp = (blockIdx.x * blockDim.x + threadIdx.x) >> 5;
    const int nwarps = (gridDim.x * blockDim.x) >> 5;

    for (int e0 = gwarp * 4; e0 < NE; e0 += nwarps * 4) {
        int    sn[4], dn[4];
        float  w[4];
        float4 u[4], v[4];
        int cnt = (NE - e0 < 4) ? (NE - e0) : 4;
        #pragma unroll
        for (int j = 0; j < 4; j++) {
            int e = e0 + j;
            if (j < cnt) {
                sn[j] = __ldg(ei + e); dn[j] = __ldg(ei + NE + e); w[j] = __ldg(ea + e);
            } else { sn[j] = 0; dn[j] = 0; w[j] = 0.f; }
        }
        #pragma unroll
        for (int j = 0; j < 4; j++) {
            u[j] = ((const float4*)(g_U + (size_t)sn[j] * H))[lane];
            v[j] = ((const float4*)(g_V + (size_t)dn[j] * H))[lane];
        }
        #pragma unroll
        for (int j = 0; j < 4; j++) {
            if (j < cnt) {
                float a0 = fmaxf(u[j].x + v[j].x, 0.f) * w[j];
                float a1 = fmaxf(u[j].y + v[j].y, 0.f) * w[j];
                float a2 = fmaxf(u[j].z + v[j].z, 0.f) * w[j];
                float a3 = fmaxf(u[j].w + v[j].w, 0.f) * w[j];
                float* p = g_S + (size_t)dn[j] * H + 4 * lane;
                asm volatile("red.global.add.v4.f32 [%0], {%1,%2,%3,%4};"
                             :: "l"(p), "f"(a0), "f"(a1), "f"(a2), "f"(a3) : "memory");
                if (lane == 0)
                    asm volatile("red.global.add.f32 [%0], %1;"
                                 :: "l"(g_sumw + dn[j]), "f"(w[j]) : "memory");
            }
        }
    }
}

// ---------------- GEMM2: out = x + S@W2 + b2*sumw ----------------
__global__ __launch_bounds__(32 * GW, 1)
void gemm2_kernel(const float* __restrict__ x,
                  const float* __restrict__ W2,   // [128,128]
                  const float* __restrict__ b2,
                  float* __restrict__ out)
{
    extern __shared__ float smem[];
    float* sW = smem;                 // 128*128 = 64 KB
    float* sS = sW + H * H;           // 64 KB

    {
        const float4* g = (const float4*)W2;
        float4* s = (float4*)sW;
        for (int i = threadIdx.x; i < H * H / 4; i += blockDim.x) s[i] = g[i];
    }
    __syncthreads();

    const int warp = threadIdx.x >> 5, lane = threadIdx.x & 31;
    float* myS = sS + warp * (8 * H);

    const float4 b2v = ((const float4*)b2)[lane];

    for (int tile = blockIdx.x; tile < NTILES_N; tile += GRID_G) {
        const int rbase = tile * TILE_R + warp * 8;

        #pragma unroll
        for (int e = 0; e < 8; e++) {
            int r = rbase + e;
            if (r < NN)
                ((float4*)(myS + e * H))[lane] = ((const float4*)(g_S + (size_t)r * H))[lane];
        }
        __syncwarp();

        unsigned long long acc[8][2];
        #pragma unroll
        for (int e = 0; e < 8; e++) { acc[e][0] = 0ull; acc[e][1] = 0ull; }

        for (int k = 0; k < H; k += 4) {
            unsigned long long wP[4][2];
            #pragma unroll
            for (int j = 0; j < 4; j++) {
                float4 w = *(const float4*)(sW + (k + j) * H + 4 * lane);
                wP[j][0] = pk2(w.x, w.y); wP[j][1] = pk2(w.z, w.w);
            }
            #pragma unroll
            for (int e = 0; e < 8; e++) {
                float4 h = *(const float4*)(myS + e * H + k);
                unsigned long long h0 = pk2(h.x, h.x), h1 = pk2(h.y, h.y);
                unsigned long long h2 = pk2(h.z, h.z), h3 = pk2(h.w, h.w);
                acc[e][0] = ffma2(h0, wP[0][0], acc[e][0]);
                acc[e][1] = ffma2(h0, wP[0][1], acc[e][1]);
                acc[e][0] = ffma2(h1, wP[1][0], acc[e][0]);
                acc[e][1] = ffma2(h1, wP[1][1], acc[e][1]);
                acc[e][0] = ffma2(h2, wP[2][0], acc[e][0]);
                acc[e][1] = ffma2(h2, wP[2][1], acc[e][1]);
                acc[e][0] = ffma2(h3, wP[3][0], acc[e][0]);
                acc[e][1] = ffma2(h3, wP[3][1], acc[e][1]);
            }
        }

        #pragma unroll
        for (int e = 0; e < 8; e++) {
            int r = rbase + e;
            if (r < NN) {
                float  sw = g_sumw[r];
                float4 xr = ((const float4*)(x + (size_t)r * H))[lane];
                float2 a = upk2(acc[e][0]), b = upk2(acc[e][1]);
                float4 o = make_float4(xr.x + a.x + b2v.x * sw,
                                       xr.y + a.y + b2v.y * sw,
                                       xr.z + b.x + b2v.z * sw,
                                       xr.w + b.y + b2v.w * sw);
                ((float4*)(out + (size_t)r * H))[lane] = o;
            }
        }
        __syncwarp();
    }
}

// ---------------- launch ----------------
extern "C" void kernel_launch(void* const* d_in, const int* in_sizes, int n_in,
                              void* d_out, int out_size) {
    (void)in_sizes; (void)n_in; (void)out_size;
    const float* x  = (const float*)d_in[0];
    const int*   ei = (const int*)d_in[1];
    const float* ea = (const float*)d_in[2];
    const float* W1 = (const float*)d_in[3];
    const float* b1 = (const float*)d_in[4];
    const float* W2 = (const float*)d_in[5];
    const float* b2 = (const float*)d_in[6];
    float* out = (float*)d_out;

    const int nz = NN * H / 4 + NN / 4;
    zero_kernel<<<(nz + 255) / 256, 256>>>();

    const size_t smem1 = (size_t)(256 * H + TILE_R * H) * sizeof(float);   // 192 KB
    cudaFuncSetAttribute(gemm1_kernel, cudaFuncAttributeMaxDynamicSharedMemorySize, (int)smem1);
    gemm1_kernel<<<GRID_G, 32 * GW, smem1>>>(x, W1, b1);

    edge_kernel<<<2048, 256>>>(ei, ea);

    const size_t smem2 = (size_t)(H * H + TILE_R * H) * sizeof(float);     // 128 KB
    cudaFuncSetAttribute(gemm2_kernel, cudaFuncAttributeMaxDynamicSharedMemorySize, (int)smem2);
    gemm2_kernel<<<GRID_G, 32 * GW, smem2>>>(x, W2, b2, out);
}

// round 7
// speedup vs baseline: 5.1806x; 1.0879x over previous
#include <cuda_runtime.h>
#include <cuda_bf16.h>
#include <cstdint>

#define H        128
#define NE       500000
#define NN       50000
#define APAD     68                  // padded b32-pair row stride (64 + 4)

// ---------------- scratch (__device__ globals) ----------------
__device__ __align__(16) float g_U[NN * H];
__device__ __align__(16) float g_V[NN * H];
__device__ __align__(16) float g_S[NN * H];
__device__ __align__(16) float g_sumw[NN];
__device__ __align__(16) uint32_t g_B1u[32768];   // [hl][kt8][nt32][lane32][2]
__device__ __align__(16) uint32_t g_B2u[16384];   // [hl][kt8][nt16][lane32][2]

// ---------------- helpers ----------------
__device__ __forceinline__ void splitpair(float v0, float v1, uint32_t& h, uint32_t& l) {
    __nv_bfloat162 hh = __floats2bfloat162_rn(v0, v1);     // x = v0 (low 16b)
    float r0 = v0 - __bfloat162float(hh.x);
    float r1 = v1 - __bfloat162float(hh.y);
    __nv_bfloat162 ll = __floats2bfloat162_rn(r0, r1);
    h = *(uint32_t*)&hh;
    l = *(uint32_t*)&ll;
}

__device__ __forceinline__ void mma_bf16(float* d,
                                         uint32_t a0, uint32_t a1, uint32_t a2, uint32_t a3,
                                         uint32_t b0, uint32_t b1) {
    asm("mma.sync.aligned.m16n8k16.row.col.f32.bf16.bf16.f32 "
        "{%0,%1,%2,%3}, {%4,%5,%6,%7}, {%8,%9}, {%0,%1,%2,%3};"
        : "+f"(d[0]), "+f"(d[1]), "+f"(d[2]), "+f"(d[3])
        : "r"(a0), "r"(a1), "r"(a2), "r"(a3), "r"(b0), "r"(b1));
}

// ---------------- zero S and sumw ----------------
__global__ void zero_kernel() {
    int i = blockIdx.x * blockDim.x + threadIdx.x;
    if (i < NN * H / 4) ((float4*)g_S)[i] = make_float4(0.f, 0.f, 0.f, 0.f);
    else if (i < NN * H / 4 + NN / 4)
        ((float4*)g_sumw)[i - NN * H / 4] = make_float4(0.f, 0.f, 0.f, 0.f);
}

// ---------------- prep: weight matrices -> bf16 hi/lo fragment images ----------------
__global__ void prep_B1(const float* __restrict__ W1) {   // [256,128]; Bcat[k][n]
    int i = blockIdx.x * blockDim.x + threadIdx.x;
    if (i >= 8192) return;
    int kt = i >> 10, nt = (i >> 5) & 31, lane = i & 31;
    int g = lane >> 2, tig = lane & 3;
    int n = nt * 8 + g;
    int k0 = kt * 16 + 2 * tig;
    float w[4];
    #pragma unroll
    for (int j = 0; j < 4; j++) {
        int k = k0 + (j >> 1) * 8 + (j & 1);
        w[j] = (n < 128) ? W1[(size_t)k * 128 + n]
                         : W1[(size_t)(128 + k) * 128 + (n - 128)];
    }
    uint32_t b0h, b0l, b1h, b1l;
    splitpair(w[0], w[1], b0h, b0l);
    splitpair(w[2], w[3], b1h, b1l);
    int base = ((kt * 32 + nt) * 32 + lane) * 2;
    g_B1u[base] = b0h; g_B1u[base + 1] = b1h;
    g_B1u[16384 + base] = b0l; g_B1u[16384 + base + 1] = b1l;
}

__global__ void prep_B2(const float* __restrict__ W2) {   // [128,128]
    int i = blockIdx.x * blockDim.x + threadIdx.x;
    if (i >= 4096) return;
    int kt = i >> 9, nt = (i >> 5) & 15, lane = i & 31;
    int g = lane >> 2, tig = lane & 3;
    int n = nt * 8 + g;
    int k0 = kt * 16 + 2 * tig;
    float w[4];
    #pragma unroll
    for (int j = 0; j < 4; j++) {
        int k = k0 + (j >> 1) * 8 + (j & 1);
        w[j] = W2[(size_t)k * 128 + n];
    }
    uint32_t b0h, b0l, b1h, b1l;
    splitpair(w[0], w[1], b0h, b0l);
    splitpair(w[2], w[3], b1h, b1l);
    int base = ((kt * 16 + nt) * 32 + lane) * 2;
    g_B2u[base] = b0h; g_B2u[base + 1] = b1h;
    g_B2u[8192 + base] = b0l; g_B2u[8192 + base + 1] = b1l;
}

// ---------------- GEMM1 (mma): U = x@W1a + b1 ; V = x@W1b ----------------
// 8 warps x 16 rows = 128 rows per CTA; N = 256 (U || V)
__global__ __launch_bounds__(256, 1)
void gemm1_kernel(const float* __restrict__ x, const float* __restrict__ b1) {
    extern __shared__ uint32_t sm[];
    uint32_t* sAh = sm;              // 128*68 = 8704
    uint32_t* sAl = sm + 8704;
    uint32_t* sB  = sm + 17408;      // 32768 words
    const int tid = threadIdx.x;

    {   // copy B fragment image (128 KB)
        const float4* src = (const float4*)g_B1u;
        float4* dst = (float4*)sB;
        for (int i = tid; i < 8192; i += 256) dst[i] = src[i];
    }
    const int rbase = blockIdx.x * 128;

    // load + split A (x rows)
    for (int i = tid; i < 128 * 32; i += 256) {
        int r = i >> 5, c4 = i & 31;
        int grow = rbase + r;
        float4 v = (grow < NN) ? ((const float4*)x)[(size_t)grow * 32 + c4]
                               : make_float4(0.f, 0.f, 0.f, 0.f);
        uint32_t h01, l01, h23, l23;
        splitpair(v.x, v.y, h01, l01);
        splitpair(v.z, v.w, h23, l23);
        *(uint2*)(sAh + r * APAD + 2 * c4) = make_uint2(h01, h23);
        *(uint2*)(sAl + r * APAD + 2 * c4) = make_uint2(l01, l23);
    }
    __syncthreads();

    const int warp = tid >> 5, lane = tid & 31, g = lane >> 2, tig = lane & 3;
    const uint32_t* a0h = sAh + (warp * 16 + g) * APAD;
    const uint32_t* a1h = sAh + (warp * 16 + g + 8) * APAD;
    const uint32_t* a0l = sAl + (warp * 16 + g) * APAD;
    const uint32_t* a1l = sAl + (warp * 16 + g + 8) * APAD;
    const int row0 = rbase + warp * 16 + g;
    const int row1 = row0 + 8;

    for (int nc = 0; nc < 8; nc++) {
        float acc[4][4] = {};
        #pragma unroll
        for (int kt = 0; kt < 8; kt++) {
            uint32_t ah0 = a0h[kt * 8 + tig], ah1 = a1h[kt * 8 + tig];
            uint32_t ah2 = a0h[kt * 8 + tig + 4], ah3 = a1h[kt * 8 + tig + 4];
            uint32_t al0 = a0l[kt * 8 + tig], al1 = a1l[kt * 8 + tig];
            uint32_t al2 = a0l[kt * 8 + tig + 4], al3 = a1l[kt * 8 + tig + 4];
            #pragma unroll
            for (int nt = 0; nt < 4; nt++) {
                int ntg = nc * 4 + nt;
                const uint32_t* bp = sB + ((kt * 32 + ntg) * 32 + lane) * 2;
                uint2 bh = *(const uint2*)bp;
                uint2 bl = *(const uint2*)(bp + 16384);
                mma_bf16(acc[nt], ah0, ah1, ah2, ah3, bh.x, bh.y);
                mma_bf16(acc[nt], al0, al1, al2, al3, bh.x, bh.y);
                mma_bf16(acc[nt], ah0, ah1, ah2, ah3, bl.x, bl.y);
            }
        }
        #pragma unroll
        for (int nt = 0; nt < 4; nt++) {
            int ncol = (nc * 4 + nt) * 8 + 2 * tig;
            if (ncol < 128) {
                float bb0 = __ldg(b1 + ncol), bb1 = __ldg(b1 + ncol + 1);
                if (row0 < NN)
                    *(float2*)(g_U + (size_t)row0 * H + ncol) =
                        make_float2(acc[nt][0] + bb0, acc[nt][1] + bb1);
                if (row1 < NN)
                    *(float2*)(g_U + (size_t)row1 * H + ncol) =
                        make_float2(acc[nt][2] + bb0, acc[nt][3] + bb1);
            } else {
                int vc = ncol - 128;
                if (row0 < NN)
                    *(float2*)(g_V + (size_t)row0 * H + vc) =
                        make_float2(acc[nt][0], acc[nt][1]);
                if (row1 < NN)
                    *(float2*)(g_V + (size_t)row1 * H + vc) =
                        make_float2(acc[nt][2], acc[nt][3]);
            }
        }
    }
}

// ---------------- edge kernel ----------------
__global__ __launch_bounds__(256)
void edge_kernel(const int* __restrict__ ei, const float* __restrict__ ea)
{
    const int lane = threadIdx.x & 31;
    const int gwarp = (blockIdx.x * blockDim.x + threadIdx.x) >> 5;
    const int nwarps = (gridDim.x * blockDim.x) >> 5;

    for (int e0 = gwarp * 4; e0 < NE; e0 += nwarps * 4) {
        int sn[4], dn[4]; float w[4]; float4 u[4], v[4];
        int cnt = (NE - e0 < 4) ? (NE - e0) : 4;
        #pragma unroll
        for (int j = 0; j < 4; j++) {
            int e = e0 + j;
            if (j < cnt) { sn[j] = __ldg(ei + e); dn[j] = __ldg(ei + NE + e); w[j] = __ldg(ea + e); }
            else { sn[j] = 0; dn[j] = 0; w[j] = 0.f; }
        }
        #pragma unroll
        for (int j = 0; j < 4; j++) {
            u[j] = ((const float4*)(g_U + (size_t)sn[j] * H))[lane];
            v[j] = ((const float4*)(g_V + (size_t)dn[j] * H))[lane];
        }
        #pragma unroll
        for (int j = 0; j < 4; j++) {
            if (j < cnt) {
                float a0 = fmaxf(u[j].x + v[j].x, 0.f) * w[j];
                float a1 = fmaxf(u[j].y + v[j].y, 0.f) * w[j];
                float a2 = fmaxf(u[j].z + v[j].z, 0.f) * w[j];
                float a3 = fmaxf(u[j].w + v[j].w, 0.f) * w[j];
                float* p = g_S + (size_t)dn[j] * H + 4 * lane;
                asm volatile("red.global.add.v4.f32 [%0], {%1,%2,%3,%4};"
                             :: "l"(p), "f"(a0), "f"(a1), "f"(a2), "f"(a3) : "memory");
                if (lane == 0)
                    asm volatile("red.global.add.f32 [%0], %1;"
                                 :: "l"(g_sumw + dn[j]), "f"(w[j]) : "memory");
            }
        }
    }
}

// ---------------- GEMM2 (mma): out = x + S@W2 + b2*sumw ----------------
// 16 warps x 16 rows = 256 rows per CTA; N = 128
__global__ __launch_bounds__(512, 1)
void gemm2_kernel(const float* __restrict__ x, const float* __restrict__ b2,
                  float* __restrict__ out) {
    extern __shared__ uint32_t sm[];
    uint32_t* sAh = sm;               // 256*68 = 17408
    uint32_t* sAl = sm + 17408;
    uint32_t* sB  = sm + 34816;       // 16384 words
    const int tid = threadIdx.x;

    {   // copy B2 fragment image (64 KB)
        const float4* src = (const float4*)g_B2u;
        float4* dst = (float4*)sB;
        for (int i = tid; i < 4096; i += 512) dst[i] = src[i];
    }
    const int rbase = blockIdx.x * 256;

    for (int i = tid; i < 256 * 32; i += 512) {
        int r = i >> 5, c4 = i & 31;
        int grow = rbase + r;
        float4 v = (grow < NN) ? ((const float4*)g_S)[(size_t)grow * 32 + c4]
                               : make_float4(0.f, 0.f, 0.f, 0.f);
        uint32_t h01, l01, h23, l23;
        splitpair(v.x, v.y, h01, l01);
        splitpair(v.z, v.w, h23, l23);
        *(uint2*)(sAh + r * APAD + 2 * c4) = make_uint2(h01, h23);
        *(uint2*)(sAl + r * APAD + 2 * c4) = make_uint2(l01, l23);
    }
    __syncthreads();

    const int warp = tid >> 5, lane = tid & 31, g = lane >> 2, tig = lane & 3;
    const uint32_t* a0h = sAh + (warp * 16 + g) * APAD;
    const uint32_t* a1h = sAh + (warp * 16 + g + 8) * APAD;
    const uint32_t* a0l = sAl + (warp * 16 + g) * APAD;
    const uint32_t* a1l = sAl + (warp * 16 + g + 8) * APAD;
    const int row0 = rbase + warp * 16 + g;
    const int row1 = row0 + 8;
    const float sw0 = (row0 < NN) ? g_sumw[row0] : 0.f;
    const float sw1 = (row1 < NN) ? g_sumw[row1] : 0.f;

    for (int nc = 0; nc < 4; nc++) {
        float acc[4][4] = {};
        #pragma unroll
        for (int kt = 0; kt < 8; kt++) {
            uint32_t ah0 = a0h[kt * 8 + tig], ah1 = a1h[kt * 8 + tig];
            uint32_t ah2 = a0h[kt * 8 + tig + 4], ah3 = a1h[kt * 8 + tig + 4];
            uint32_t al0 = a0l[kt * 8 + tig], al1 = a1l[kt * 8 + tig];
            uint32_t al2 = a0l[kt * 8 + tig + 4], al3 = a1l[kt * 8 + tig + 4];
            #pragma unroll
            for (int nt = 0; nt < 4; nt++) {
                int ntg = nc * 4 + nt;
                const uint32_t* bp = sB + ((kt * 16 + ntg) * 32 + lane) * 2;
                uint2 bh = *(const uint2*)bp;
                uint2 bl = *(const uint2*)(bp + 8192);
                mma_bf16(acc[nt], ah0, ah1, ah2, ah3, bh.x, bh.y);
                mma_bf16(acc[nt], al0, al1, al2, al3, bh.x, bh.y);
                mma_bf16(acc[nt], ah0, ah1, ah2, ah3, bl.x, bl.y);
            }
        }
        #pragma unroll
        for (int nt = 0; nt < 4; nt++) {
            int ncol = (nc * 4 + nt) * 8 + 2 * tig;
            float bb0 = __ldg(b2 + ncol), bb1 = __ldg(b2 + ncol + 1);
            if (row0 < NN) {
                float2 xr = *(const float2*)(x + (size_t)row0 * H + ncol);
                *(float2*)(out + (size_t)row0 * H + ncol) =
                    make_float2(xr.x + acc[nt][0] + bb0 * sw0,
                                xr.y + acc[nt][1] + bb1 * sw0);
            }
            if (row1 < NN) {
                float2 xr = *(const float2*)(x + (size_t)row1 * H + ncol);
                *(float2*)(out + (size_t)row1 * H + ncol) =
                    make_float2(xr.x + acc[nt][2] + bb0 * sw1,
                                xr.y + acc[nt][3] + bb1 * sw1);
            }
        }
    }
}

// ---------------- launch ----------------
extern "C" void kernel_launch(void* const* d_in, const int* in_sizes, int n_in,
                              void* d_out, int out_size) {
    (void)in_sizes; (void)n_in; (void)out_size;
    const float* x  = (const float*)d_in[0];
    const int*   ei = (const int*)d_in[1];
    const float* ea = (const float*)d_in[2];
    const float* W1 = (const float*)d_in[3];
    const float* b1 = (const float*)d_in[4];
    const float* W2 = (const float*)d_in[5];
    const float* b2 = (const float*)d_in[6];
    float* out = (float*)d_out;

    const int nz = NN * H / 4 + NN / 4;
    zero_kernel<<<(nz + 255) / 256, 256>>>();
    prep_B1<<<32, 256>>>(W1);
    prep_B2<<<16, 256>>>(W2);

    const size_t smem1 = (size_t)(17408 + 32768) * 4;   // 196 KB
    cudaFuncSetAttribute(gemm1_kernel, cudaFuncAttributeMaxDynamicSharedMemorySize, (int)smem1);
    gemm1_kernel<<<(NN + 127) / 128, 256, smem1>>>(x, b1);

    edge_kernel<<<2048, 256>>>(ei, ea);

    const size_t smem2 = (size_t)(34816 + 16384) * 4;   // 200 KB
    cudaFuncSetAttribute(gemm2_kernel, cudaFuncAttributeMaxDynamicSharedMemorySize, (int)smem2);
    gemm2_kernel<<<(NN + 255) / 256, 512, smem2>>>(x, b2, out);
}

// round 9
// speedup vs baseline: 5.9909x; 1.1564x over previous
#include <cuda_runtime.h>
#include <cuda_bf16.h>
#include <cstdint>

#define H        128
#define NE       500000
#define NN       50000
#define APAD     68                  // padded b32-pair row stride (64 + 4)

// ---------------- scratch (__device__ globals) ----------------
__device__ __align__(16) float g_U[NN * H];
__device__ __align__(16) float g_V[NN * H];
__device__ __align__(16) float g_S[NN * H];
__device__ __align__(16) float g_sumw[NN];
__device__ __align__(16) uint32_t g_B1u[32768];   // [hl][kt8][nt32][lane32][2]
__device__ __align__(16) uint32_t g_B2u[16384];   // [hl][kt8][nt16][lane32][2]

// ---------------- helpers ----------------
__device__ __forceinline__ void splitpair(float v0, float v1, uint32_t& h, uint32_t& l) {
    __nv_bfloat162 hh = __floats2bfloat162_rn(v0, v1);
    float r0 = v0 - __bfloat162float(hh.x);
    float r1 = v1 - __bfloat162float(hh.y);
    __nv_bfloat162 ll = __floats2bfloat162_rn(r0, r1);
    h = *(uint32_t*)&hh;
    l = *(uint32_t*)&ll;
}

__device__ __forceinline__ void mma_bf16(float* d,
                                         uint32_t a0, uint32_t a1, uint32_t a2, uint32_t a3,
                                         uint32_t b0, uint32_t b1) {
    asm("mma.sync.aligned.m16n8k16.row.col.f32.bf16.bf16.f32 "
        "{%0,%1,%2,%3}, {%4,%5,%6,%7}, {%8,%9}, {%0,%1,%2,%3};"
        : "+f"(d[0]), "+f"(d[1]), "+f"(d[2]), "+f"(d[3])
        : "r"(a0), "r"(a1), "r"(a2), "r"(a3), "r"(b0), "r"(b1));
}

// ---------------- zero S and sumw ----------------
__global__ void zero_kernel() {
    int i = blockIdx.x * blockDim.x + threadIdx.x;
    if (i < NN * H / 4) ((float4*)g_S)[i] = make_float4(0.f, 0.f, 0.f, 0.f);
    else if (i < NN * H / 4 + NN / 4)
        ((float4*)g_sumw)[i - NN * H / 4] = make_float4(0.f, 0.f, 0.f, 0.f);
}

// ---------------- prep: weight matrices -> bf16 hi/lo fragment images ----------------
__global__ void prep_B1(const float* __restrict__ W1) {   // [256,128]; Bcat[k][n]
    int i = blockIdx.x * blockDim.x + threadIdx.x;
    if (i >= 8192) return;
    int kt = i >> 10, nt = (i >> 5) & 31, lane = i & 31;
    int g = lane >> 2, tig = lane & 3;
    int n = nt * 8 + g;
    int k0 = kt * 16 + 2 * tig;
    float w[4];
    #pragma unroll
    for (int j = 0; j < 4; j++) {
        int k = k0 + (j >> 1) * 8 + (j & 1);
        w[j] = (n < 128) ? W1[(size_t)k * 128 + n]
                         : W1[(size_t)(128 + k) * 128 + (n - 128)];
    }
    uint32_t b0h, b0l, b1h, b1l;
    splitpair(w[0], w[1], b0h, b0l);
    splitpair(w[2], w[3], b1h, b1l);
    int base = ((kt * 32 + nt) * 32 + lane) * 2;
    g_B1u[base] = b0h; g_B1u[base + 1] = b1h;
    g_B1u[16384 + base] = b0l; g_B1u[16384 + base + 1] = b1l;
}

__global__ void prep_B2(const float* __restrict__ W2) {   // [128,128]
    int i = blockIdx.x * blockDim.x + threadIdx.x;
    if (i >= 4096) return;
    int kt = i >> 9, nt = (i >> 5) & 15, lane = i & 31;
    int g = lane >> 2, tig = lane & 3;
    int n = nt * 8 + g;
    int k0 = kt * 16 + 2 * tig;
    float w[4];
    #pragma unroll
    for (int j = 0; j < 4; j++) {
        int k = k0 + (j >> 1) * 8 + (j & 1);
        w[j] = W2[(size_t)k * 128 + n];
    }
    uint32_t b0h, b0l, b1h, b1l;
    splitpair(w[0], w[1], b0h, b0l);
    splitpair(w[2], w[3], b1h, b1l);
    int base = ((kt * 16 + nt) * 32 + lane) * 2;
    g_B2u[base] = b0h; g_B2u[base + 1] = b1h;
    g_B2u[8192 + base] = b0l; g_B2u[8192 + base + 1] = b1l;
}

// ---------------- GEMM1 (mma): U = x@W1a + b1 ; V = x@W1b ----------------
// 8 warps x 16 rows = 128 rows per CTA; N = 256 (U || V); B via __ldg + prefetch
__global__ __launch_bounds__(256, 2)
void gemm1_kernel(const float* __restrict__ x, const float* __restrict__ b1) {
    extern __shared__ uint32_t sm[];
    uint32_t* sAh = sm;              // 128*68 = 8704
    uint32_t* sAl = sm + 8704;
    const int tid = threadIdx.x;
    const int rbase = blockIdx.x * 128;

    // load + split A (x rows)
    for (int i = tid; i < 128 * 32; i += 256) {
        int r = i >> 5, c4 = i & 31;
        int grow = rbase + r;
        float4 v = (grow < NN) ? ((const float4*)x)[(size_t)grow * 32 + c4]
                               : make_float4(0.f, 0.f, 0.f, 0.f);
        uint32_t h01, l01, h23, l23;
        splitpair(v.x, v.y, h01, l01);
        splitpair(v.z, v.w, h23, l23);
        *(uint2*)(sAh + r * APAD + 2 * c4) = make_uint2(h01, h23);
        *(uint2*)(sAl + r * APAD + 2 * c4) = make_uint2(l01, l23);
    }
    __syncthreads();

    const int warp = tid >> 5, lane = tid & 31, g = lane >> 2, tig = lane & 3;
    const uint32_t* a0h = sAh + (warp * 16 + g) * APAD;
    const uint32_t* a1h = sAh + (warp * 16 + g + 8) * APAD;
    const uint32_t* a0l = sAl + (warp * 16 + g) * APAD;
    const uint32_t* a1l = sAl + (warp * 16 + g + 8) * APAD;
    const int row0 = rbase + warp * 16 + g;
    const int row1 = row0 + 8;
    const uint2* gB = (const uint2*)g_B1u;   // hi [0,8192), lo [8192,16384)

    for (int nc = 0; nc < 8; nc++) {
        float acc[4][4] = {};
        uint2 bh[4], bl[4];
        #pragma unroll
        for (int nt = 0; nt < 4; nt++) {
            int idx = (nc * 4 + nt) * 32 + lane;       // kt = 0
            bh[nt] = __ldg(gB + idx);
            bl[nt] = __ldg(gB + idx + 8192);
        }
        #pragma unroll
        for (int kt = 0; kt < 8; kt++) {
            uint2 nbh[4], nbl[4];
            if (kt < 7) {
                #pragma unroll
                for (int nt = 0; nt < 4; nt++) {
                    int idx = ((kt + 1) * 32 + nc * 4 + nt) * 32 + lane;
                    nbh[nt] = __ldg(gB + idx);
                    nbl[nt] = __ldg(gB + idx + 8192);
                }
            }
            uint32_t ah0 = a0h[kt * 8 + tig], ah1 = a1h[kt * 8 + tig];
            uint32_t ah2 = a0h[kt * 8 + tig + 4], ah3 = a1h[kt * 8 + tig + 4];
            uint32_t al0 = a0l[kt * 8 + tig], al1 = a1l[kt * 8 + tig];
            uint32_t al2 = a0l[kt * 8 + tig + 4], al3 = a1l[kt * 8 + tig + 4];
            #pragma unroll
            for (int nt = 0; nt < 4; nt++) {
                mma_bf16(acc[nt], ah0, ah1, ah2, ah3, bh[nt].x, bh[nt].y);
                mma_bf16(acc[nt], al0, al1, al2, al3, bh[nt].x, bh[nt].y);
                mma_bf16(acc[nt], ah0, ah1, ah2, ah3, bl[nt].x, bl[nt].y);
            }
            if (kt < 7) {
                #pragma unroll
                for (int nt = 0; nt < 4; nt++) { bh[nt] = nbh[nt]; bl[nt] = nbl[nt]; }
            }
        }
        #pragma unroll
        for (int nt = 0; nt < 4; nt++) {
            int ncol = (nc * 4 + nt) * 8 + 2 * tig;
            if (ncol < 128) {
                float bb0 = __ldg(b1 + ncol), bb1 = __ldg(b1 + ncol + 1);
                if (row0 < NN)
                    *(float2*)(g_U + (size_t)row0 * H + ncol) =
                        make_float2(acc[nt][0] + bb0, acc[nt][1] + bb1);
                if (row1 < NN)
                    *(float2*)(g_U + (size_t)row1 * H + ncol) =
                        make_float2(acc[nt][2] + bb0, acc[nt][3] + bb1);
            } else {
                int vc = ncol - 128;
                if (row0 < NN)
                    *(float2*)(g_V + (size_t)row0 * H + vc) =
                        make_float2(acc[nt][0], acc[nt][1]);
                if (row1 < NN)
                    *(float2*)(g_V + (size_t)row1 * H + vc) =
                        make_float2(acc[nt][2], acc[nt][3]);
            }
        }
    }
}

// ---------------- edge kernel ----------------
__global__ __launch_bounds__(256)
void edge_kernel(const int* __restrict__ ei, const float* __restrict__ ea)
{
    const int lane = threadIdx.x & 31;
    const int gwarp = (blockIdx.x * blockDim.x + threadIdx.x) >> 5;
    const int nwarps = (gridDim.x * blockDim.x) >> 5;

    for (int e0 = gwarp * 4; e0 < NE; e0 += nwarps * 4) {
        int sn[4], dn[4]; float w[4]; float4 u[4], v[4];
        int cnt = (NE - e0 < 4) ? (NE - e0) : 4;
        #pragma unroll
        for (int j = 0; j < 4; j++) {
            int e = e0 + j;
            if (j < cnt) { sn[j] = __ldg(ei + e); dn[j] = __ldg(ei + NE + e); w[j] = __ldg(ea + e); }
            else { sn[j] = 0; dn[j] = 0; w[j] = 0.f; }
        }
        #pragma unroll
        for (int j = 0; j < 4; j++) {
            u[j] = ((const float4*)(g_U + (size_t)sn[j] * H))[lane];
            v[j] = ((const float4*)(g_V + (size_t)dn[j] * H))[lane];
        }
        #pragma unroll
        for (int j = 0; j < 4; j++) {
            if (j < cnt) {
                float a0 = fmaxf(u[j].x + v[j].x, 0.f) * w[j];
                float a1 = fmaxf(u[j].y + v[j].y, 0.f) * w[j];
                float a2 = fmaxf(u[j].z + v[j].z, 0.f) * w[j];
                float a3 = fmaxf(u[j].w + v[j].w, 0.f) * w[j];
                float* p = g_S + (size_t)dn[j] * H + 4 * lane;
                asm volatile("red.global.add.v4.f32 [%0], {%1,%2,%3,%4};"
                             :: "l"(p), "f"(a0), "f"(a1), "f"(a2), "f"(a3) : "memory");
                if (lane == 0)
                    asm volatile("red.global.add.f32 [%0], %1;"
                                 :: "l"(g_sumw + dn[j]), "f"(w[j]) : "memory");
            }
        }
    }
}

// ---------------- GEMM2 (mma): out = x + S@W2 + b2*sumw ----------------
// 8 warps x 16 rows = 128 rows per CTA; N = 128; B via __ldg + prefetch
__global__ __launch_bounds__(256, 2)
void gemm2_kernel(const float* __restrict__ x, const float* __restrict__ b2,
                  float* __restrict__ out) {
    extern __shared__ uint32_t sm[];
    uint32_t* sAh = sm;               // 128*68 = 8704
    uint32_t* sAl = sm + 8704;
    const int tid = threadIdx.x;
    const int rbase = blockIdx.x * 128;

    for (int i = tid; i < 128 * 32; i += 256) {
        int r = i >> 5, c4 = i & 31;
        int grow = rbase + r;
        float4 v = (grow < NN) ? ((const float4*)g_S)[(size_t)grow * 32 + c4]
                               : make_float4(0.f, 0.f, 0.f, 0.f);
        uint32_t h01, l01, h23, l23;
        splitpair(v.x, v.y, h01, l01);
        splitpair(v.z, v.w, h23, l23);
        *(uint2*)(sAh + r * APAD + 2 * c4) = make_uint2(h01, h23);
        *(uint2*)(sAl + r * APAD + 2 * c4) = make_uint2(l01, l23);
    }
    __syncthreads();

    const int warp = tid >> 5, lane = tid & 31, g = lane >> 2, tig = lane & 3;
    const uint32_t* a0h = sAh + (warp * 16 + g) * APAD;
    const uint32_t* a1h = sAh + (warp * 16 + g + 8) * APAD;
    const uint32_t* a0l = sAl + (warp * 16 + g) * APAD;
    const uint32_t* a1l = sAl + (warp * 16 + g + 8) * APAD;
    const int row0 = rbase + warp * 16 + g;
    const int row1 = row0 + 8;
    const float sw0 = (row0 < NN) ? g_sumw[row0] : 0.f;
    const float sw1 = (row1 < NN) ? g_sumw[row1] : 0.f;
    const uint2* gB = (const uint2*)g_B2u;   // hi [0,4096), lo [4096,8192)

    for (int nc = 0; nc < 4; nc++) {
        float acc[4][4] = {};
        uint2 bh[4], bl[4];
        #pragma unroll
        for (int nt = 0; nt < 4; nt++) {
            int idx = (nc * 4 + nt) * 32 + lane;       // kt = 0
            bh[nt] = __ldg(gB + idx);
            bl[nt] = __ldg(gB + idx + 4096);
        }
        #pragma unroll
        for (int kt = 0; kt < 8; kt++) {
            uint2 nbh[4], nbl[4];
            if (kt < 7) {
                #pragma unroll
                for (int nt = 0; nt < 4; nt++) {
                    int idx = ((kt + 1) * 16 + nc * 4 + nt) * 32 + lane;
                    nbh[nt] = __ldg(gB + idx);
                    nbl[nt] = __ldg(gB + idx + 4096);
                }
            }
            uint32_t ah0 = a0h[kt * 8 + tig], ah1 = a1h[kt * 8 + tig];
            uint32_t ah2 = a0h[kt * 8 + tig + 4], ah3 = a1h[kt * 8 + tig + 4];
            uint32_t al0 = a0l[kt * 8 + tig], al1 = a1l[kt * 8 + tig];
            uint32_t al2 = a0l[kt * 8 + tig + 4], al3 = a1l[kt * 8 + tig + 4];
            #pragma unroll
            for (int nt = 0; nt < 4; nt++) {
                mma_bf16(acc[nt], ah0, ah1, ah2, ah3, bh[nt].x, bh[nt].y);
                mma_bf16(acc[nt], al0, al1, al2, al3, bh[nt].x, bh[nt].y);
                mma_bf16(acc[nt], ah0, ah1, ah2, ah3, bl[nt].x, bl[nt].y);
            }
            if (kt < 7) {
                #pragma unroll
                for (int nt = 0; nt < 4; nt++) { bh[nt] = nbh[nt]; bl[nt] = nbl[nt]; }
            }
        }
        #pragma unroll
        for (int nt = 0; nt < 4; nt++) {
            int ncol = (nc * 4 + nt) * 8 + 2 * tig;
            float bb0 = __ldg(b2 + ncol), bb1 = __ldg(b2 + ncol + 1);
            if (row0 < NN) {
                float2 xr = *(const float2*)(x + (size_t)row0 * H + ncol);
                *(float2*)(out + (size_t)row0 * H + ncol) =
                    make_float2(xr.x + acc[nt][0] + bb0 * sw0,
                                xr.y + acc[nt][1] + bb1 * sw0);
            }
            if (row1 < NN) {
                float2 xr = *(const float2*)(x + (size_t)row1 * H + ncol);
                *(float2*)(out + (size_t)row1 * H + ncol) =
                    make_float2(xr.x + acc[nt][2] + bb0 * sw1,
                                xr.y + acc[nt][3] + bb1 * sw1);
            }
        }
    }
}

// ---------------- launch ----------------
extern "C" void kernel_launch(void* const* d_in, const int* in_sizes, int n_in,
                              void* d_out, int out_size) {
    (void)in_sizes; (void)n_in; (void)out_size;
    const float* x  = (const float*)d_in[0];
    const int*   ei = (const int*)d_in[1];
    const float* ea = (const float*)d_in[2];
    const float* W1 = (const float*)d_in[3];
    const float* b1 = (const float*)d_in[4];
    const float* W2 = (const float*)d_in[5];
    const float* b2 = (const float*)d_in[6];
    float* out = (float*)d_out;

    const int nz = NN * H / 4 + NN / 4;
    zero_kernel<<<(nz + 255) / 256, 256>>>();
    prep_B1<<<32, 256>>>(W1);
    prep_B2<<<16, 256>>>(W2);

    const size_t smemA = (size_t)(2 * 8704) * 4;        // 68 KB (A hi/lo)
    cudaFuncSetAttribute(gemm1_kernel, cudaFuncAttributeMaxDynamicSharedMemorySize, (int)smemA);
    gemm1_kernel<<<(NN + 127) / 128, 256, smemA>>>(x, b1);

    edge_kernel<<<2048, 256>>>(ei, ea);

    cudaFuncSetAttribute(gemm2_kernel, cudaFuncAttributeMaxDynamicSharedMemorySize, (int)smemA);
    gemm2_kernel<<<(NN + 127) / 128, 256, smemA>>>(x, b2, out);
}